// round 3
// baseline (speedup 1.0000x reference)
#include <cuda_runtime.h>

// Geometry: (1, D=24, H=24, W=16, C=2); N = 9216 voxels.
#define NV   9216
#define NTHR 576     // = 24*24 lines for the x-pass; 18 warps

// Taylor rank for exp(I_i*I_j/9): k = 0..4 (next term ~1.4e-7 relative)
// c_k = (1/9)^k / k!
// Fields per iteration: f=2k+c (k=0..4, c=0..1) bilateral, f=10+c spatial.

__device__ float g_fbuf[2][12][NV];   // ping-pong blurred fields
__device__ float g_nrm[6][NV];        // 0..4: bilateral norm basis, 5: spatial norm

// ---------------------------------------------------------------------------
// Build per-axis Gaussian kernel matrices in smem. k24 serves both y and z
// (D == H == 24), k16 serves x (W == 16).
// ---------------------------------------------------------------------------
__device__ __forceinline__ void build_k(float* k24, float* k16, float theta) {
    float inv2 = 0.5f / (theta * theta);
    for (int idx = threadIdx.x; idx < 576; idx += blockDim.x) {
        float d = (float)(idx / 24) - (float)(idx % 24);
        k24[idx] = expf(-d * d * inv2);
    }
    for (int idx = threadIdx.x; idx < 256; idx += blockDim.x) {
        float d = (float)(idx / 16) - (float)(idx % 16);
        k16[idx] = expf(-d * d * inv2);
    }
}

// ---------------------------------------------------------------------------
// Full 3-axis dense separable filter, in place in shared memory.
// Layout: buf[(z*24 + y)*16 + x].
//   x-pass: 576 lines of 16  (one per thread)
//   y-pass: 384 lines of 24  (threads 0..383)
//   z-pass: 384 lines of 24
// Each line is owned by exactly one thread; loads complete into registers
// before the in-place writes, so no double buffer is needed.
// ---------------------------------------------------------------------------
__device__ void blur3(float* buf, const float* k24, const float* k16) {
    int tid = threadIdx.x;
    __syncthreads();   // input prep / kernel build -> reads

    // ---- x-pass ----
    {
        float in[16];
        float4* line = (float4*)(buf + tid * 16);
        #pragma unroll
        for (int j = 0; j < 4; ++j) {
            float4 v = line[j];
            in[4*j+0] = v.x; in[4*j+1] = v.y; in[4*j+2] = v.z; in[4*j+3] = v.w;
        }
        float out[16];
        for (int x = 0; x < 16; ++x) {
            float acc = 0.f;
            #pragma unroll
            for (int xp = 0; xp < 16; ++xp) acc += k16[x*16 + xp] * in[xp];
            out[x] = acc;
        }
        #pragma unroll
        for (int j = 0; j < 4; ++j)
            line[j] = make_float4(out[4*j+0], out[4*j+1], out[4*j+2], out[4*j+3]);
    }
    __syncthreads();

    // ---- y-pass ----
    if (tid < 384) {
        int z = tid >> 4, x = tid & 15;
        float in[24];
        #pragma unroll
        for (int y = 0; y < 24; ++y) in[y] = buf[(z*24 + y)*16 + x];
        for (int y = 0; y < 24; ++y) {
            float acc = 0.f;
            #pragma unroll
            for (int yp = 0; yp < 24; ++yp) acc += k24[y*24 + yp] * in[yp];
            buf[(z*24 + y)*16 + x] = acc;
        }
    }
    __syncthreads();

    // ---- z-pass ----
    if (tid < 384) {
        int y = tid >> 4, x = tid & 15;
        float in[24];
        #pragma unroll
        for (int z = 0; z < 24; ++z) in[z] = buf[(z*24 + y)*16 + x];
        for (int z = 0; z < 24; ++z) {
            float acc = 0.f;
            #pragma unroll
            for (int zp = 0; zp < 24; ++zp) acc += k24[z*24 + zp] * in[zp];
            buf[(z*24 + y)*16 + x] = acc;
        }
    }
    __syncthreads();   // writes -> strided global writeout
}

// ---------------------------------------------------------------------------
// Per-voxel message reconstruction from blurred fields.
//   spatial_out_c  = fin[10+c] / nrm[5]
//   bilateral_out_c = (sum_k c_k I^k fin[2k+c]) / (sum_k c_k I^k nrm[k])
//   (the e^{-a I^2} prefactor cancels between numerator and normalizer)
//   m_c = spatial_out_c * ws_c + bilateral_out_c * wb_c
// ---------------------------------------------------------------------------
__device__ __forceinline__ void compute_msgs(
    int i, float Iv, const float* __restrict__ fin0,
    float ws0, float ws1, float wb0, float wb1,
    float& m0, float& m1)
{
    const float ck[5] = {1.0f, 0.111111111f, 0.0061728395f,
                         2.28623686e-4f, 6.35066338e-6f};
    float p = 1.0f, nb = 0.f, b0 = 0.f, b1 = 0.f;
    #pragma unroll
    for (int k = 0; k < 5; ++k) {
        float cp = ck[k] * p;
        nb += cp * g_nrm[k][i];
        b0 += cp * fin0[(2*k + 0) * NV + i];
        b1 += cp * fin0[(2*k + 1) * NV + i];
        p *= Iv;
    }
    float inv_nb = 1.0f / nb;
    float inv_ns = 1.0f / g_nrm[5][i];
    m0 = fin0[10*NV + i] * inv_ns * ws0 + b0 * inv_nb * wb0;
    m1 = fin0[11*NV + i] * inv_ns * ws1 + b1 * inv_nb * wb1;
}

// ---------------------------------------------------------------------------
// Normalizer fields: blur of the all-ones input (spatial) and of the
// bilateral basis e^{-a I^2} I^k (k = 0..4). One block per field.
// ---------------------------------------------------------------------------
__global__ __launch_bounds__(NTHR)
void norm_kernel(const float* __restrict__ rgb) {
    __shared__ __align__(16) float buf[NV];
    __shared__ float k24[576];
    __shared__ float k16[256];
    int b = blockIdx.x;
    bool bil = (b < 5);
    build_k(k24, k16, bil ? 160.0f : 3.0f);
    const float A = 1.0f / 18.0f;
    for (int i = threadIdx.x; i < NV; i += NTHR) {
        float val = 1.0f;
        if (bil) {
            float Iv = rgb[i];
            float pw = 1.0f;
            for (int kk = 0; kk < b; ++kk) pw *= Iv;
            val = __expf(-A * Iv * Iv) * pw;
        }
        buf[i] = val;
    }
    blur3(buf, k24, k16);
    for (int i = threadIdx.x; i < NV; i += NTHR) g_nrm[b][i] = buf[i];
}

// ---------------------------------------------------------------------------
// One CRF iteration step: each of 12 blocks rebuilds q_{t-1} on the fly from
// the previous iteration's fields (or uses u when first=1), forms its basis
// input, runs the full 3-axis blur in smem, and writes its field to the
// ping-pong output buffer. Reads and writes go to DIFFERENT buffers, so the
// 12 concurrent blocks cannot race.
// ---------------------------------------------------------------------------
__global__ __launch_bounds__(NTHR)
void blur_kernel(const float* __restrict__ u, const float* __restrict__ rgb,
                 const float* __restrict__ ws, const float* __restrict__ wb,
                 const float* __restrict__ Mc,
                 int sIn, int sOut, int first)
{
    __shared__ __align__(16) float buf[NV];
    __shared__ float k24[576];
    __shared__ float k16[256];

    int f = blockIdx.x;
    bool bil = (f < 10);
    build_k(k24, k16, bil ? 160.0f : 3.0f);

    int kpow = bil ? (f >> 1) : 0;
    int c    = bil ? (f & 1) : (f - 10);

    float ws0 = ws[0], ws1 = ws[1], wb0 = wb[0], wb1 = wb[1];
    float M00 = Mc[0], M01 = Mc[1], M10 = Mc[2], M11 = Mc[3];
    const float* fin0 = &g_fbuf[sIn][0][0];
    float* fout = &g_fbuf[sOut][f][0];
    const float A = 1.0f / 18.0f;

    for (int i = threadIdx.x; i < NV; i += NTHR) {
        float Iv = rgb[i];
        float q;
        if (first) {
            q = u[2*i + c];
        } else {
            float m0, m1;
            compute_msgs(i, Iv, fin0, ws0, ws1, wb0, wb1, m0, m1);
            float pw = (c == 0) ? (m0 * M00 + m1 * M01)
                                : (m0 * M10 + m1 * M11);
            q = u[2*i + c] - pw;
        }
        float val = q;
        if (bil) {
            float e = __expf(-A * Iv * Iv);
            float pI = 1.0f;
            for (int kk = 0; kk < kpow; ++kk) pI *= Iv;
            val = e * pI * q;
        }
        buf[i] = val;
    }

    blur3(buf, k24, k16);

    for (int i = threadIdx.x; i < NV; i += NTHR) fout[i] = buf[i];
}

// ---------------------------------------------------------------------------
// Final combine: q_5 = u - message @ compat^T, written to d_out [N, 2].
// ---------------------------------------------------------------------------
__global__ void final_kernel(const float* __restrict__ u, const float* __restrict__ rgb,
                             const float* __restrict__ ws, const float* __restrict__ wb,
                             const float* __restrict__ Mc,
                             float* __restrict__ out, int sIn)
{
    int i = blockIdx.x * blockDim.x + threadIdx.x;
    if (i >= NV) return;
    float m0, m1;
    compute_msgs(i, rgb[i], &g_fbuf[sIn][0][0], ws[0], ws[1], wb[0], wb[1], m0, m1);
    out[2*i + 0] = u[2*i + 0] - (m0 * Mc[0] + m1 * Mc[1]);
    out[2*i + 1] = u[2*i + 1] - (m0 * Mc[2] + m1 * Mc[3]);
}

// ---------------------------------------------------------------------------
// Inputs (metadata order): unaries[18432] f32, rgb[9216] f32,
// spatial_ker_weights[2] f32, bilateral_ker_weights[2] f32,
// compatibility_matrix[4] f32 (row-major). Output: float32 [18432].
// ---------------------------------------------------------------------------
extern "C" void kernel_launch(void* const* d_in, const int* in_sizes, int n_in,
                              void* d_out, int out_size) {
    const float* u   = (const float*)d_in[0];
    const float* rgb = (const float*)d_in[1];
    const float* ws  = (const float*)d_in[2];
    const float* wb  = (const float*)d_in[3];
    const float* Mc  = (const float*)d_in[4];
    float* out = (float*)d_out;

    norm_kernel<<<6, NTHR>>>(rgb);
    // 5 iterations: step s writes g_fbuf[s & 1 ^ ...] via explicit ping-pong.
    blur_kernel<<<12, NTHR>>>(u, rgb, ws, wb, Mc, /*sIn*/0, /*sOut*/0, /*first*/1);
    blur_kernel<<<12, NTHR>>>(u, rgb, ws, wb, Mc, 0, 1, 0);
    blur_kernel<<<12, NTHR>>>(u, rgb, ws, wb, Mc, 1, 0, 0);
    blur_kernel<<<12, NTHR>>>(u, rgb, ws, wb, Mc, 0, 1, 0);
    blur_kernel<<<12, NTHR>>>(u, rgb, ws, wb, Mc, 1, 0, 0);
    final_kernel<<<(NV + 255) / 256, 256>>>(u, rgb, ws, wb, Mc, out, 0);
}

// round 4
// speedup vs baseline: 2.6044x; 2.6044x over previous
#include <cuda_runtime.h>

// Geometry: (1, D=24, H=24, W=16, C=2); N = 9216 voxels.
#define NV   9216
#define NB   144     // blocks; <= 148 SMs so all co-resident (safe grid barrier)
#define NT   384     // threads per block (one per slab/plane element)

// Taylor rank-5 factorization of the bilateral intensity kernel:
//   exp(-(Ii-Ij)^2/18) = e^{-Ii^2/18} e^{-Ij^2/18} * sum_k c_k Ii^k Ij^k,
//   c_k = (1/9)^k / k!,  truncation error ~1.4e-7.
// Fields per iteration: f=2k+c (k=0..4, c=0..1) bilateral, f=10+c spatial.

__device__ float g_buf[2][12][NV];   // ping-pong blurred fields
__device__ float g_nrm[6][NV];       // 0..4: bilateral norm basis, 5: spatial norm
__device__ int   g_count;            // barrier arrival counter (returns to 0)
__device__ int   g_epoch;            // barrier epoch (monotonic, replay-safe)

// ---------------------------------------------------------------------------
// Grid barrier: release/acquire via epoch counter. Epoch base is read at
// kernel entry, so state is consistent across CUDA-graph replays.
// ---------------------------------------------------------------------------
__device__ __forceinline__ int ld_acq(const int* p) {
    int v; asm volatile("ld.global.acquire.gpu.b32 %0, [%1];" : "=r"(v) : "l"(p) : "memory");
    return v;
}
__device__ __forceinline__ void st_rel(int* p, int v) {
    asm volatile("st.global.release.gpu.b32 [%0], %1;" :: "l"(p), "r"(v) : "memory");
}
__device__ __forceinline__ void gridbar(int& target) {
    __syncthreads();
    if (threadIdx.x == 0) {
        target += 1;
        __threadfence();                       // release this block's writes
        int old = atomicAdd(&g_count, 1);
        if (old == NB - 1) {
            __threadfence();                   // acquire everyone's writes
            g_count = 0;                       // ordered before release below
            st_rel(&g_epoch, target);
        } else {
            while (ld_acq(&g_epoch) < target) {}
        }
    }
    __syncthreads();
}

// ---------------------------------------------------------------------------
// x-pass + y-pass of one z-slab (24y x 16x = 384 elems), fully in smem.
// Kernel matrices are symmetric, so we index them transposed to make every
// smem access either broadcast or stride-1 (conflict-free).
// ---------------------------------------------------------------------------
__device__ __forceinline__ void xy_blur_store(
    float val, float* s, const float* k24, const float* k16, float* gdst)
{
    int t = threadIdx.x, y = t >> 4, x = t & 15;
    s[t] = val;
    __syncthreads();
    float a = 0.f;
    #pragma unroll
    for (int xp = 0; xp < 16; ++xp) a += k16[xp * 16 + x] * s[(y << 4) + xp];
    __syncthreads();
    s[t] = a;
    __syncthreads();
    float bacc = 0.f;
    #pragma unroll
    for (int yp = 0; yp < 24; ++yp) bacc += k24[yp * 24 + y] * s[(yp << 4) + x];
    gdst[t] = bacc;          // coalesced: gdst = field + z*384
    __syncthreads();         // protect s before next unit reuses it
}

// ---------------------------------------------------------------------------
// z-pass of one y-plane (24z x 16x), in place in global via smem staging.
// Blocks own disjoint (field, y) planes, so in-place is race-free.
// ---------------------------------------------------------------------------
__device__ __forceinline__ void z_blur(float* s, const float* k24, float* fbase, int y)
{
    int t = threadIdx.x, z = t >> 4, x = t & 15;
    s[t] = fbase[(t >> 4) * 384 + y * 16 + (t & 15)];   // element (zp=t/16, x)
    __syncthreads();
    float acc = 0.f;
    #pragma unroll
    for (int zp = 0; zp < 24; ++zp) acc += k24[zp * 24 + z] * s[(zp << 4) + x];
    __syncthreads();                                    // all reads done
    fbase[z * 384 + y * 16 + x] = acc;
    __syncthreads();
}

// ---------------------------------------------------------------------------
// Per-voxel message reconstruction from blurred fields (e^{-aI^2} prefactor
// cancels between numerator and normalizer).
// ---------------------------------------------------------------------------
__device__ __forceinline__ void compute_msgs(
    int i, float Iv, const float* __restrict__ fin0,
    float ws0, float ws1, float wb0, float wb1,
    float& m0, float& m1)
{
    const float ck[5] = {1.0f, 0.111111111f, 0.0061728395f,
                         2.28623686e-4f, 6.35066338e-6f};
    float p = 1.0f, nb = 0.f, b0 = 0.f, b1 = 0.f;
    #pragma unroll
    for (int k = 0; k < 5; ++k) {
        float cp = ck[k] * p;
        nb += cp * g_nrm[k][i];
        b0 += cp * fin0[(2 * k + 0) * NV + i];
        b1 += cp * fin0[(2 * k + 1) * NV + i];
        p *= Iv;
    }
    float inv_nb = 1.0f / nb;
    float inv_ns = 1.0f / g_nrm[5][i];
    m0 = fin0[10 * NV + i] * inv_ns * ws0 + b0 * inv_nb * wb0;
    m1 = fin0[11 * NV + i] * inv_ns * ws1 + b1 * inv_nb * wb1;
}

// ---------------------------------------------------------------------------
// The whole CRF in ONE persistent kernel. Per iteration:
//   phase1: 288 units (field f, slab z): build input, x+y blur  -> g_buf[pp]
//   gridbar
//   phase2: 288 units (field f, plane y): z blur in place on g_buf[pp]
//   gridbar
// Norm fields ride along with iteration 1 (which only needs u).
// ---------------------------------------------------------------------------
__global__ void __launch_bounds__(NT)
crf_kernel(const float* __restrict__ u, const float* __restrict__ rgb,
           const float* __restrict__ ws, const float* __restrict__ wb,
           const float* __restrict__ Mc, float* __restrict__ out)
{
    __shared__ __align__(16) float s[NT];
    __shared__ float kb24[576], ks24[576];   // bilateral (theta=160) / spatial (theta=3)
    __shared__ float kb16[256], ks16[256];

    const int b = blockIdx.x, t = threadIdx.x;
    int target = 0;
    if (t == 0) target = ld_acq(&g_epoch);   // replay-safe epoch base

    // Build both per-axis Gaussian kernel matrices.
    for (int idx = t; idx < 576; idx += NT) {
        float d = (float)(idx / 24) - (float)(idx % 24);
        float d2 = d * d;
        kb24[idx] = __expf(-d2 * (0.5f / (160.f * 160.f)));
        ks24[idx] = __expf(-d2 * (0.5f / 9.f));
    }
    for (int idx = t; idx < 256; idx += NT) {
        float d = (float)(idx / 16) - (float)(idx % 16);
        float d2 = d * d;
        kb16[idx] = __expf(-d2 * (0.5f / (160.f * 160.f)));
        ks16[idx] = __expf(-d2 * (0.5f / 9.f));
    }
    // (first __syncthreads inside xy_blur_store orders kmat writes vs reads)

    const float ws0 = ws[0], ws1 = ws[1], wb0 = wb[0], wb1 = wb[1];
    const float M00 = Mc[0], M01 = Mc[1], M10 = Mc[2], M11 = Mc[3];
    const float A = 1.0f / 18.0f;

    // ---- Phase A: iteration-1 phase1 (input = u) + norm phase1 ----
    #pragma unroll
    for (int uu = 0; uu < 2; ++uu) {
        int un = b + uu * NB;                  // 0..287
        int f = un / 24, z = un % 24;
        bool bil = (f < 10);
        int c = bil ? (f & 1) : (f - 10);
        int kp = bil ? (f >> 1) : 0;
        int i = z * 384 + t;
        float q = u[2 * i + c];
        float val = q;
        if (bil) {
            float Iv = rgb[i];
            float e = __expf(-A * Iv * Iv);
            float p = 1.f;
            for (int kk = 0; kk < kp; ++kk) p *= Iv;
            val = e * p * q;
        }
        xy_blur_store(val, s, bil ? kb24 : ks24, bil ? kb16 : ks16,
                      &g_buf[0][f][z * 384]);
    }
    {   // norm phase1: 6 fields x 24 slabs = 144 units = NB
        int f = b / 24, z = b % 24;
        bool bil = (f < 5);
        int i = z * 384 + t;
        float val = 1.f;
        if (bil) {
            float Iv = rgb[i];
            float e = __expf(-A * Iv * Iv);
            float p = 1.f;
            for (int kk = 0; kk < f; ++kk) p *= Iv;
            val = e * p;
        }
        xy_blur_store(val, s, bil ? kb24 : ks24, bil ? kb16 : ks16,
                      &g_nrm[f][z * 384]);
    }
    gridbar(target);

    // ---- Phase B: iteration-1 z-pass + norm z-pass ----
    #pragma unroll
    for (int uu = 0; uu < 2; ++uu) {
        int un = b + uu * NB;
        int f = un / 24, y = un % 24;
        z_blur(s, (f < 10) ? kb24 : ks24, &g_buf[0][f][0], y);
    }
    {
        int f = b / 24, y = b % 24;
        z_blur(s, (f < 5) ? kb24 : ks24, &g_nrm[f][0], y);
    }
    gridbar(target);

    // ---- Iterations 2..5 ----
    for (int it = 2; it <= 5; ++it) {
        int pp = (it - 1) & 1, sp = pp ^ 1;
        const float* src = &g_buf[sp][0][0];
        #pragma unroll
        for (int uu = 0; uu < 2; ++uu) {
            int un = b + uu * NB;
            int f = un / 24, z = un % 24;
            bool bil = (f < 10);
            int c = bil ? (f & 1) : (f - 10);
            int kp = bil ? (f >> 1) : 0;
            int i = z * 384 + t;
            float Iv = rgb[i];
            float m0, m1;
            compute_msgs(i, Iv, src, ws0, ws1, wb0, wb1, m0, m1);
            float pw = (c == 0) ? (m0 * M00 + m1 * M01)
                                : (m0 * M10 + m1 * M11);
            float q = u[2 * i + c] - pw;
            float val = q;
            if (bil) {
                float e = __expf(-A * Iv * Iv);
                float p = 1.f;
                for (int kk = 0; kk < kp; ++kk) p *= Iv;
                val = e * p * q;
            }
            xy_blur_store(val, s, bil ? kb24 : ks24, bil ? kb16 : ks16,
                          &g_buf[pp][f][z * 384]);
        }
        gridbar(target);
        #pragma unroll
        for (int uu = 0; uu < 2; ++uu) {
            int un = b + uu * NB;
            int f = un / 24, y = un % 24;
            z_blur(s, (f < 10) ? kb24 : ks24, &g_buf[pp][f][0], y);
        }
        gridbar(target);
    }

    // ---- Final combine: q5 = u - message @ compat^T (iter-5 fields in buf 0) ----
    if (b < 24) {
        int i = b * 384 + t;
        float m0, m1;
        compute_msgs(i, rgb[i], &g_buf[0][0][0], ws0, ws1, wb0, wb1, m0, m1);
        float2 o;
        o.x = u[2 * i + 0] - (m0 * M00 + m1 * M01);
        o.y = u[2 * i + 1] - (m0 * M10 + m1 * M11);
        reinterpret_cast<float2*>(out)[i] = o;
    }
}

// ---------------------------------------------------------------------------
// Inputs (metadata order): unaries[18432] f32, rgb[9216] f32,
// spatial_ker_weights[2] f32, bilateral_ker_weights[2] f32,
// compatibility_matrix[4] f32 (row-major). Output: float32 [18432].
// ---------------------------------------------------------------------------
extern "C" void kernel_launch(void* const* d_in, const int* in_sizes, int n_in,
                              void* d_out, int out_size) {
    const float* u   = (const float*)d_in[0];
    const float* rgb = (const float*)d_in[1];
    const float* ws  = (const float*)d_in[2];
    const float* wb  = (const float*)d_in[3];
    const float* Mc  = (const float*)d_in[4];
    crf_kernel<<<NB, NT>>>(u, rgb, ws, wb, Mc, (float*)d_out);
}